// round 12
// baseline (speedup 1.0000x reference)
#include <cuda_runtime.h>
#include <cuda_fp16.h>
#include <cstdint>
#include <cstddef>

// Problem constants
#define B_   8
#define C_   32
#define F_   32
#define T_   4000
#define CH_  16
#define D_   512
#define KSCALE 0.04419417382415922f   // 1/sqrt(512)
#define EPS_ 1e-5f

// ---------------- device scratch (static, no allocation) ----------------
__device__ __half g_q   [(size_t)B_ * T_ * D_];      // [b][t][d]
__device__ __half g_k   [(size_t)B_ * T_ * D_];      // [b][t][d] (pre-scaled)
__device__ __half g_vT  [(size_t)B_ * D_ * T_];      // [b][d][t]
__device__ __half g_mask[(size_t)B_ * T_ * T_];      // [b][t][s]
__device__ float  g_sa  [(size_t)B_ * T_ * D_];      // [b][t][d]

__device__ __forceinline__ uint32_t smem_u32(const void* p) {
    uint32_t a;
    asm("{ .reg .u64 t; cvta.to.shared.u64 t, %1; cvt.u32.u64 %0, t; }"
        : "=r"(a) : "l"(p));
    return a;
}

// =========================================================================
// Kernel A: fused q/k/v 1x1-conv + BN + PReLU, output in token layout.
// =========================================================================
__global__ __launch_bounds__(1024) void qkv_kernel(
    const float* __restrict__ x,
    const float* __restrict__ W, const float* __restrict__ bias,
    const float* __restrict__ gamma, const float* __restrict__ beta,
    const float* __restrict__ mean,  const float* __restrict__ var,
    const float* __restrict__ alpha)
{
    __shared__ float sW[3 * 16 * 32];
    __shared__ float sB[3 * 16];
    __shared__ float sAl[3];
    __shared__ __align__(16) __half stage[32 * 520];

    const int tid = threadIdx.x;
    const int b = blockIdx.y;
    const int t0 = blockIdx.x * 32;

    for (int idx = tid; idx < 3 * 16 * 32; idx += 1024) {
        int nc = idx >> 5;
        float s = gamma[nc] * rsqrtf(var[nc] + EPS_);
        sW[idx] = W[idx] * s;
    }
    if (tid < 48) {
        float s = gamma[tid] * rsqrtf(var[tid] + EPS_);
        sB[tid] = bias[tid] * s + beta[tid] - mean[tid] * s;
    }
    if (tid < 3) sAl[tid] = alpha[tid];
    __syncthreads();

    const int tl = tid & 31;
    const int f  = tid >> 5;
    const int t  = t0 + tl;

    float xv[32];
#pragma unroll
    for (int i = 0; i < 32; i++)
        xv[i] = x[((size_t)(b * 32 + i) * 32 + f) * 4000 + t];

    for (int n = 0; n < 2; n++) {
#pragma unroll
        for (int ch = 0; ch < 16; ch++) {
            float acc = sB[n * 16 + ch];
#pragma unroll
            for (int i = 0; i < 32; i++) acc += sW[(n * 16 + ch) * 32 + i] * xv[i];
            acc = acc > 0.f ? acc : sAl[n] * acc;
            if (n == 1) acc *= KSCALE;
            stage[tl * 520 + ch * 32 + f] = __float2half(acc);
        }
        __syncthreads();
        {
            __half* dst = (n == 0) ? g_q : g_k;
            const int w = tid >> 5;
            const int l = tid & 31;
            const __half* src = stage + w * 520 + l * 16;
            __half* dptr = dst + ((size_t)(b * 4000 + t0 + w) * 512) + l * 16;
            int4 v0 = *(const int4*)(src);
            int4 v1 = *(const int4*)(src + 8);
            *(int4*)(dptr) = v0;
            *(int4*)(dptr + 8) = v1;
        }
        __syncthreads();
    }
#pragma unroll
    for (int ch = 0; ch < 16; ch++) {
        float acc = sB[2 * 16 + ch];
#pragma unroll
        for (int i = 0; i < 32; i++) acc += sW[(2 * 16 + ch) * 32 + i] * xv[i];
        acc = acc > 0.f ? acc : sAl[2] * acc;
        int d = ch * 32 + f;
        g_vT[((size_t)b * 512 + d) * 4000 + t] = __float2half(acc);
    }
}

// ======================= shared mma helpers =======================
__device__ __forceinline__ void ldm_x4(uint32_t* r, uint32_t addr) {
    asm volatile("ldmatrix.sync.aligned.m8n8.x4.shared.b16 {%0,%1,%2,%3}, [%4];"
                 : "=r"(r[0]), "=r"(r[1]), "=r"(r[2]), "=r"(r[3]) : "r"(addr));
}
__device__ __forceinline__ void mma16816(float* c, const uint32_t* a,
                                         uint32_t b0, uint32_t b1) {
    asm volatile(
        "mma.sync.aligned.m16n8k16.row.col.f32.f16.f16.f32 "
        "{%0,%1,%2,%3}, {%4,%5,%6,%7}, {%8,%9}, {%0,%1,%2,%3};"
        : "+f"(c[0]), "+f"(c[1]), "+f"(c[2]), "+f"(c[3])
        : "r"(a[0]), "r"(a[1]), "r"(a[2]), "r"(a[3]), "r"(b0), "r"(b1));
}
__device__ __forceinline__ void mma16816_h(uint32_t* c, const uint32_t* a,
                                           uint32_t b0, uint32_t b1) {
    asm volatile(
        "mma.sync.aligned.m16n8k16.row.col.f16.f16.f16.f16 "
        "{%0,%1}, {%2,%3,%4,%5}, {%6,%7}, {%0,%1};"
        : "+r"(c[0]), "+r"(c[1])
        : "r"(a[0]), "r"(a[1]), "r"(a[2]), "r"(a[3]), "r"(b0), "r"(b1));
}

#define STAGES 3
#define ABYTES 16384              // 128 rows x 128B (64 halves)
#define STAGEB (2 * ABYTES)       // A + B
#define SMEM_GEMM (1024 + STAGES * STAGEB)

// =========================================================================
// GEMM1: mask = sigmoid(Q K^T)  [fp16 out]  M=4000 N=4000 K=512
// 128x128 tile, BK=64, 3-stage cp.async, 256 thr, 2 CTAs/SM.
// *** fp16 accumulators: 2x tensor rate, half the acc registers. ***
// =========================================================================
__global__ __launch_bounds__(256, 2) void gemm1_hmma()
{
    constexpr int NK  = 8;       // K=512 / 64
    constexpr int LDA = 512, LDB = 512;

    extern __shared__ __align__(16) char dsm[];
    uint32_t tbase = (smem_u32(dsm) + 1023u) & ~1023u;

    const int tid  = threadIdx.x;
    const int lane = tid & 31;
    const int warp = tid >> 5;
    const int wm = warp >> 1;
    const int wn = warp & 1;

    const int bz  = blockIdx.z;
    const int bm0 = blockIdx.y * 128;
    const int bn0 = blockIdx.x * 128;
    const __half* A  = g_q + (size_t)bz * 4000 * 512;
    const __half* Bp = g_k + (size_t)bz * 4000 * 512;

    const int prow = tid >> 3;
    const int pk8  = tid & 7;
    const int psw  = (pk8 ^ (prow & 7)) << 4;

    auto issue = [&](int kt, int s) {
        uint32_t Ab = tbase + s * STAGEB;
        uint32_t Bb = Ab + ABYTES;
#pragma unroll
        for (int i = 0; i < 4; i++) {
            int row = prow + i * 32;
            int grow = bm0 + row;
            bool valid = (grow < 4000);
            const void* src = valid ? (const void*)(A + (size_t)grow * LDA + kt * 64 + pk8 * 8)
                                    : (const void*)A;
            uint32_t dst = Ab + row * 128 + psw;
            int sz = valid ? 16 : 0;
            asm volatile("cp.async.cg.shared.global [%0], [%1], 16, %2;"
                         :: "r"(dst), "l"(src), "r"(sz));
        }
#pragma unroll
        for (int i = 0; i < 4; i++) {
            int row = prow + i * 32;
            int grow = bn0 + row;
            bool valid = (grow < 4000);
            const void* src = valid ? (const void*)(Bp + (size_t)grow * LDB + kt * 64 + pk8 * 8)
                                    : (const void*)Bp;
            uint32_t dst = Bb + row * 128 + psw;
            int sz = valid ? 16 : 0;
            asm volatile("cp.async.cg.shared.global [%0], [%1], 16, %2;"
                         :: "r"(dst), "l"(src), "r"(sz));
        }
    };

    const uint32_t xr  = lane & 7;
    const uint32_t hiA = lane >> 4;
    const uint32_t hiB = (lane >> 3) & 1;
    const uint32_t aro = (wm * 32 + (lane & 15)) * 128;
    const uint32_t bro = (wn * 64 + (lane & 7) + ((lane >> 4) << 3)) * 128;

    uint32_t c[2][8][2];                       // fp16x2 accumulators
#pragma unroll
    for (int mi = 0; mi < 2; mi++)
#pragma unroll
        for (int ni = 0; ni < 8; ni++)
#pragma unroll
            for (int q = 0; q < 2; q++) c[mi][ni][q] = 0u;

#pragma unroll
    for (int s = 0; s < STAGES - 1; s++) {
        issue(s, s);
        asm volatile("cp.async.commit_group;" ::: "memory");
    }

    for (int kt = 0; kt < NK; ++kt) {
        asm volatile("cp.async.wait_group %0;" :: "n"(STAGES - 2) : "memory");
        __syncthreads();
        if (kt + STAGES - 1 < NK) issue(kt + STAGES - 1, (kt + STAGES - 1) % STAGES);
        asm volatile("cp.async.commit_group;" ::: "memory");

        uint32_t Ab = tbase + (kt % STAGES) * STAGEB;
        uint32_t abase = Ab + aro;
        uint32_t bbase = Ab + ABYTES + bro;
#pragma unroll
        for (int kk = 0; kk < 4; kk++) {
            uint32_t ca = (((uint32_t)(kk * 2) + hiA) ^ xr) << 4;
            uint32_t cb = (((uint32_t)(kk * 2) + hiB) ^ xr) << 4;
            uint32_t a[2][4];
            ldm_x4(a[0], abase + ca);
            ldm_x4(a[1], abase + 2048 + ca);
            uint32_t b[4][4];
#pragma unroll
            for (int p = 0; p < 4; p++) ldm_x4(b[p], bbase + p * 2048 + cb);
#pragma unroll
            for (int mi = 0; mi < 2; mi++)
#pragma unroll
                for (int p = 0; p < 4; p++) {
                    mma16816_h(c[mi][2 * p],     a[mi], b[p][0], b[p][1]);
                    mma16816_h(c[mi][2 * p + 1], a[mi], b[p][2], b[p][3]);
                }
        }
        __syncthreads();
    }

    // epilogue: sigmoid(x) = 0.5*tanh(0.5x)+0.5, all in half2
    const int rbase = bm0 + wm * 32 + (lane >> 2);
    const int cbase = bn0 + wn * 64 + (lane & 3) * 2;
    const __half2 half05 = __float2half2_rn(0.5f);
#pragma unroll
    for (int mi = 0; mi < 2; mi++) {
#pragma unroll
        for (int ni = 0; ni < 8; ni++) {
            int col = cbase + ni * 8;
            if (col >= 4000) continue;
            size_t cb2 = (size_t)bz * 4000 * 4000 + col;
#pragma unroll
            for (int h = 0; h < 2; h++) {
                int row = rbase + mi * 16 + h * 8;
                if (row >= 4000) continue;
                uint32_t u = c[mi][ni][h];
                __half2 hv = __hmul2(*(__half2*)&u, half05);
                uint32_t u2 = *(uint32_t*)&hv;
                asm("tanh.approx.f16x2 %0, %0;" : "+r"(u2));
                __half2 th = *(__half2*)&u2;
                __half2 r = __hfma2(th, half05, half05);
                *(uint32_t*)(g_mask + cb2 + (size_t)row * 4000) = *(uint32_t*)&r;
            }
        }
    }
}

// =========================================================================
// GEMM2: sa = mask @ V  [fp32 out]  M=4000 N=512 K=4000  (f32 acc, R8-proven)
// =========================================================================
__global__ __launch_bounds__(256, 2) void gemm2_hmma()
{
    constexpr int NK  = 63;      // ceil(4000/64)
    constexpr int LDA = 4000, LDB = 4000;
    constexpr int NMAX = 512;

    extern __shared__ __align__(16) char dsm[];
    uint32_t tbase = (smem_u32(dsm) + 1023u) & ~1023u;

    const int tid  = threadIdx.x;
    const int lane = tid & 31;
    const int warp = tid >> 5;
    const int wm = warp >> 1;
    const int wn = warp & 1;

    const int bz  = blockIdx.z;
    const int bm0 = blockIdx.y * 128;
    const int bn0 = blockIdx.x * 128;
    const __half* A  = g_mask + (size_t)bz * 4000 * 4000;
    const __half* Bp = g_vT   + (size_t)bz * 512 * 4000;

    const int prow = tid >> 3;
    const int pk8  = tid & 7;
    const int psw  = (pk8 ^ (prow & 7)) << 4;

    auto issue = [&](int kt, int s) {
        uint32_t Ab = tbase + s * STAGEB;
        uint32_t Bb = Ab + ABYTES;
        bool kv = (kt * 64 + pk8 * 8) < 4000;
#pragma unroll
        for (int i = 0; i < 4; i++) {
            int row = prow + i * 32;
            int grow = bm0 + row;
            bool valid = kv && (grow < 4000);
            const void* src = valid ? (const void*)(A + (size_t)grow * LDA + kt * 64 + pk8 * 8)
                                    : (const void*)A;
            uint32_t dst = Ab + row * 128 + psw;
            int sz = valid ? 16 : 0;
            asm volatile("cp.async.cg.shared.global [%0], [%1], 16, %2;"
                         :: "r"(dst), "l"(src), "r"(sz));
        }
#pragma unroll
        for (int i = 0; i < 4; i++) {
            int row = prow + i * 32;
            int grow = bn0 + row;
            bool valid = kv && (grow < NMAX);
            const void* src = valid ? (const void*)(Bp + (size_t)grow * LDB + kt * 64 + pk8 * 8)
                                    : (const void*)Bp;
            uint32_t dst = Bb + row * 128 + psw;
            int sz = valid ? 16 : 0;
            asm volatile("cp.async.cg.shared.global [%0], [%1], 16, %2;"
                         :: "r"(dst), "l"(src), "r"(sz));
        }
    };

    const uint32_t xr  = lane & 7;
    const uint32_t hiA = lane >> 4;
    const uint32_t hiB = (lane >> 3) & 1;
    const uint32_t aro = (wm * 32 + (lane & 15)) * 128;
    const uint32_t bro = (wn * 64 + (lane & 7) + ((lane >> 4) << 3)) * 128;

    float c[2][8][4];
#pragma unroll
    for (int mi = 0; mi < 2; mi++)
#pragma unroll
        for (int ni = 0; ni < 8; ni++)
#pragma unroll
            for (int q = 0; q < 4; q++) c[mi][ni][q] = 0.f;

#pragma unroll
    for (int s = 0; s < STAGES - 1; s++) {
        issue(s, s);
        asm volatile("cp.async.commit_group;" ::: "memory");
    }

    for (int kt = 0; kt < NK; ++kt) {
        asm volatile("cp.async.wait_group %0;" :: "n"(STAGES - 2) : "memory");
        __syncthreads();
        if (kt + STAGES - 1 < NK) issue(kt + STAGES - 1, (kt + STAGES - 1) % STAGES);
        asm volatile("cp.async.commit_group;" ::: "memory");

        uint32_t Ab = tbase + (kt % STAGES) * STAGEB;
        uint32_t abase = Ab + aro;
        uint32_t bbase = Ab + ABYTES + bro;
#pragma unroll
        for (int kk = 0; kk < 4; kk++) {
            uint32_t ca = (((uint32_t)(kk * 2) + hiA) ^ xr) << 4;
            uint32_t cb = (((uint32_t)(kk * 2) + hiB) ^ xr) << 4;
            uint32_t a[2][4];
            ldm_x4(a[0], abase + ca);
            ldm_x4(a[1], abase + 2048 + ca);
            uint32_t b[4][4];
#pragma unroll
            for (int p = 0; p < 4; p++) ldm_x4(b[p], bbase + p * 2048 + cb);
#pragma unroll
            for (int mi = 0; mi < 2; mi++)
#pragma unroll
                for (int p = 0; p < 4; p++) {
                    mma16816(c[mi][2 * p],     a[mi], b[p][0], b[p][1]);
                    mma16816(c[mi][2 * p + 1], a[mi], b[p][2], b[p][3]);
                }
        }
        __syncthreads();
    }

    const int rbase = bm0 + wm * 32 + (lane >> 2);
    const int cbase = bn0 + wn * 64 + (lane & 3) * 2;
#pragma unroll
    for (int mi = 0; mi < 2; mi++) {
#pragma unroll
        for (int ni = 0; ni < 8; ni++) {
            int col = cbase + ni * 8;
            size_t cb2 = (size_t)bz * 4000 * 512 + col;
#pragma unroll
            for (int h = 0; h < 2; h++) {
                int row = rbase + mi * 16 + h * 8;
                if (row >= 4000) continue;
                float2 v = make_float2(c[mi][ni][2 * h], c[mi][ni][2 * h + 1]);
                *(float2*)(g_sa + cb2 + (size_t)row * 512) = v;
            }
        }
    }
}

// =========================================================================
// Kernel D: enc 1x1-conv + BN + PReLU + residual.
// smem [d][t] layout (pad 33) -> conflict-free reads (R9-verified, 94us).
// =========================================================================
#define ENC_SMEM (512 * 33 * 4)
__global__ __launch_bounds__(1024) void enc_kernel(
    const float* __restrict__ x,
    const float* __restrict__ W, const float* __restrict__ bias,
    const float* __restrict__ gamma, const float* __restrict__ beta,
    const float* __restrict__ mean,  const float* __restrict__ var,
    const float* __restrict__ alpha,
    float* __restrict__ out)
{
    extern __shared__ float sSa[];            // [512][33] d-major
    __shared__ float sW[512];
    __shared__ float sB[32];
    __shared__ float sAl;

    const int tid = threadIdx.x;
    const int b = blockIdx.y;
    const int t0 = blockIdx.x * 32;

    if (tid < 512) {
        int c = tid >> 4, ch = tid & 15;
        float s = gamma[c] * rsqrtf(var[c] + EPS_);
        sW[tid] = W[c * 16 + ch] * s;
    }
    if (tid < 32) {
        float s = gamma[tid] * rsqrtf(var[tid] + EPS_);
        sB[tid] = bias[tid] * s + beta[tid] - mean[tid] * s;
    }
    if (tid == 0) sAl = alpha[0];

#pragma unroll
    for (int i = 0; i < 4; i++) {
        int v  = tid + i * 1024;
        int tr = v >> 7;
        int d4 = (v & 127) * 4;
        float4 q = *(const float4*)(g_sa + ((size_t)(b * 4000 + t0 + tr)) * 512 + d4);
        sSa[(d4 + 0) * 33 + tr] = q.x;
        sSa[(d4 + 1) * 33 + tr] = q.y;
        sSa[(d4 + 2) * 33 + tr] = q.z;
        sSa[(d4 + 3) * 33 + tr] = q.w;
    }
    __syncthreads();

    const int tl = tid & 31;
    const int f  = tid >> 5;
    const int t  = t0 + tl;

    float sv[16];
#pragma unroll
    for (int ch = 0; ch < 16; ch++) sv[ch] = sSa[(ch * 32 + f) * 33 + tl];

#pragma unroll
    for (int c = 0; c < 32; c++) {
        float acc = sB[c];
#pragma unroll
        for (int ch = 0; ch < 16; ch++) acc += sW[c * 16 + ch] * sv[ch];
        acc = acc > 0.f ? acc : sAl * acc;
        size_t o = ((size_t)((b * 32 + c) * 32 + f)) * 4000 + t;
        out[o] = acc + x[o];
    }
}

// =========================================================================
extern "C" void kernel_launch(void* const* d_in, const int* in_sizes, int n_in,
                              void* d_out, int out_size)
{
    const float* x          = (const float*)d_in[0];
    const float* qkv_W      = (const float*)d_in[1];
    const float* qkv_b      = (const float*)d_in[2];
    const float* qkv_gamma  = (const float*)d_in[3];
    const float* qkv_beta   = (const float*)d_in[4];
    const float* qkv_mean   = (const float*)d_in[5];
    const float* qkv_var    = (const float*)d_in[6];
    const float* qkv_alpha  = (const float*)d_in[7];
    const float* enc_W      = (const float*)d_in[8];
    const float* enc_b      = (const float*)d_in[9];
    const float* enc_gamma  = (const float*)d_in[10];
    const float* enc_beta   = (const float*)d_in[11];
    const float* enc_mean   = (const float*)d_in[12];
    const float* enc_var    = (const float*)d_in[13];
    const float* enc_alpha  = (const float*)d_in[14];
    float* out = (float*)d_out;

    cudaFuncSetAttribute(gemm1_hmma, cudaFuncAttributeMaxDynamicSharedMemorySize, SMEM_GEMM);
    cudaFuncSetAttribute(gemm2_hmma, cudaFuncAttributeMaxDynamicSharedMemorySize, SMEM_GEMM);
    cudaFuncSetAttribute(enc_kernel, cudaFuncAttributeMaxDynamicSharedMemorySize, ENC_SMEM);

    // 1) q/k/v conv blocks -> token-layout fp16
    qkv_kernel<<<dim3(125, 8), 1024>>>(x, qkv_W, qkv_b, qkv_gamma, qkv_beta,
                                       qkv_mean, qkv_var, qkv_alpha);
    // 2) mask = sigmoid(Q K^T)   [B,4000,4000] fp16 — fp16 accumulation
    gemm1_hmma<<<dim3(32, 32, 8), 256, SMEM_GEMM>>>();
    // 3) sa = mask @ V           [B,4000,512] fp32 — fp32 accumulation
    gemm2_hmma<<<dim3(4, 32, 8), 256, SMEM_GEMM>>>();
    // 4) enc conv block + residual
    enc_kernel<<<dim3(125, 8), 1024, ENC_SMEM>>>(x, enc_W, enc_b, enc_gamma, enc_beta,
                                                 enc_mean, enc_var, enc_alpha, out);
}

// round 13
// speedup vs baseline: 1.0134x; 1.0134x over previous
#include <cuda_runtime.h>
#include <cuda_fp16.h>
#include <cstdint>
#include <cstddef>

// Problem constants
#define B_   8
#define C_   32
#define F_   32
#define T_   4000
#define CH_  16
#define D_   512
#define KSCALE 0.04419417382415922f   // 1/sqrt(512)
#define EPS_ 1e-5f

// ---------------- device scratch (static, no allocation) ----------------
__device__ __half g_q   [(size_t)B_ * T_ * D_];      // [b][t][d]
__device__ __half g_k   [(size_t)B_ * T_ * D_];      // [b][t][d] (pre-scaled)
__device__ __half g_vT  [(size_t)B_ * D_ * T_];      // [b][d][t]
__device__ __half g_mask[(size_t)B_ * T_ * T_];      // [b][t][s]
__device__ float  g_sa  [(size_t)B_ * T_ * D_];      // [b][t][d]

__device__ __forceinline__ uint32_t smem_u32(const void* p) {
    uint32_t a;
    asm("{ .reg .u64 t; cvta.to.shared.u64 t, %1; cvt.u32.u64 %0, t; }"
        : "=r"(a) : "l"(p));
    return a;
}

// ---- no-op kernels: shift the ncu capture slot onto gemm1 ----
__global__ void noop_kernel() {}

// =========================================================================
// Kernel A: fused q/k/v 1x1-conv + BN + PReLU, output in token layout.
// =========================================================================
__global__ __launch_bounds__(1024) void qkv_kernel(
    const float* __restrict__ x,
    const float* __restrict__ W, const float* __restrict__ bias,
    const float* __restrict__ gamma, const float* __restrict__ beta,
    const float* __restrict__ mean,  const float* __restrict__ var,
    const float* __restrict__ alpha)
{
    __shared__ float sW[3 * 16 * 32];
    __shared__ float sB[3 * 16];
    __shared__ float sAl[3];
    __shared__ __align__(16) __half stage[32 * 520];

    const int tid = threadIdx.x;
    const int b = blockIdx.y;
    const int t0 = blockIdx.x * 32;

    for (int idx = tid; idx < 3 * 16 * 32; idx += 1024) {
        int nc = idx >> 5;
        float s = gamma[nc] * rsqrtf(var[nc] + EPS_);
        sW[idx] = W[idx] * s;
    }
    if (tid < 48) {
        float s = gamma[tid] * rsqrtf(var[tid] + EPS_);
        sB[tid] = bias[tid] * s + beta[tid] - mean[tid] * s;
    }
    if (tid < 3) sAl[tid] = alpha[tid];
    __syncthreads();

    const int tl = tid & 31;
    const int f  = tid >> 5;
    const int t  = t0 + tl;

    float xv[32];
#pragma unroll
    for (int i = 0; i < 32; i++)
        xv[i] = x[((size_t)(b * 32 + i) * 32 + f) * 4000 + t];

    for (int n = 0; n < 2; n++) {
#pragma unroll
        for (int ch = 0; ch < 16; ch++) {
            float acc = sB[n * 16 + ch];
#pragma unroll
            for (int i = 0; i < 32; i++) acc += sW[(n * 16 + ch) * 32 + i] * xv[i];
            acc = acc > 0.f ? acc : sAl[n] * acc;
            if (n == 1) acc *= KSCALE;
            stage[tl * 520 + ch * 32 + f] = __float2half(acc);
        }
        __syncthreads();
        {
            __half* dst = (n == 0) ? g_q : g_k;
            const int w = tid >> 5;
            const int l = tid & 31;
            const __half* src = stage + w * 520 + l * 16;
            __half* dptr = dst + ((size_t)(b * 4000 + t0 + w) * 512) + l * 16;
            int4 v0 = *(const int4*)(src);
            int4 v1 = *(const int4*)(src + 8);
            *(int4*)(dptr) = v0;
            *(int4*)(dptr + 8) = v1;
        }
        __syncthreads();
    }
#pragma unroll
    for (int ch = 0; ch < 16; ch++) {
        float acc = sB[2 * 16 + ch];
#pragma unroll
        for (int i = 0; i < 32; i++) acc += sW[(2 * 16 + ch) * 32 + i] * xv[i];
        acc = acc > 0.f ? acc : sAl[2] * acc;
        int d = ch * 32 + f;
        g_vT[((size_t)b * 512 + d) * 4000 + t] = __float2half(acc);
    }
}

// ======================= shared mma helpers =======================
__device__ __forceinline__ void ldm_x4(uint32_t* r, uint32_t addr) {
    asm volatile("ldmatrix.sync.aligned.m8n8.x4.shared.b16 {%0,%1,%2,%3}, [%4];"
                 : "=r"(r[0]), "=r"(r[1]), "=r"(r[2]), "=r"(r[3]) : "r"(addr));
}
__device__ __forceinline__ void mma16816(float* c, const uint32_t* a,
                                         uint32_t b0, uint32_t b1) {
    asm volatile(
        "mma.sync.aligned.m16n8k16.row.col.f32.f16.f16.f32 "
        "{%0,%1,%2,%3}, {%4,%5,%6,%7}, {%8,%9}, {%0,%1,%2,%3};"
        : "+f"(c[0]), "+f"(c[1]), "+f"(c[2]), "+f"(c[3])
        : "r"(a[0]), "r"(a[1]), "r"(a[2]), "r"(a[3]), "r"(b0), "r"(b1));
}

#define STAGES 3
#define ABYTES 16384              // 128 rows x 128B (64 halves)
#define STAGEB (2 * ABYTES)       // A + B
#define SMEM_GEMM (1024 + STAGES * STAGEB)

// =========================================================================
// GEMM1: mask = sigmoid(Q K^T)  [fp16 out]  M=4000 N=4000 K=512
// 128x128 tile, BK=64, 3-stage cp.async, 256 thr, 2 CTAs/SM, f32 acc.
// Epilogue: smem-staged, coalesced 2-rows-per-instr STG.128.
// =========================================================================
__global__ __launch_bounds__(256, 2) void gemm1_hmma()
{
    constexpr int NK  = 8;       // K=512 / 64
    constexpr int LDA = 512, LDB = 512;

    extern __shared__ __align__(16) char dsm[];
    uint32_t tbase = (smem_u32(dsm) + 1023u) & ~1023u;

    const int tid  = threadIdx.x;
    const int lane = tid & 31;
    const int warp = tid >> 5;
    const int wm = warp >> 1;
    const int wn = warp & 1;

    const int bz  = blockIdx.z;
    const int bm0 = blockIdx.y * 128;
    const int bn0 = blockIdx.x * 128;
    const __half* A  = g_q + (size_t)bz * 4000 * 512;
    const __half* Bp = g_k + (size_t)bz * 4000 * 512;

    const int prow = tid >> 3;
    const int pk8  = tid & 7;
    const int psw  = (pk8 ^ (prow & 7)) << 4;

    auto issue = [&](int kt, int s) {
        uint32_t Ab = tbase + s * STAGEB;
        uint32_t Bb = Ab + ABYTES;
#pragma unroll
        for (int i = 0; i < 4; i++) {
            int row = prow + i * 32;
            int grow = bm0 + row;
            bool valid = (grow < 4000);
            const void* src = valid ? (const void*)(A + (size_t)grow * LDA + kt * 64 + pk8 * 8)
                                    : (const void*)A;
            uint32_t dst = Ab + row * 128 + psw;
            int sz = valid ? 16 : 0;
            asm volatile("cp.async.cg.shared.global [%0], [%1], 16, %2;"
                         :: "r"(dst), "l"(src), "r"(sz));
        }
#pragma unroll
        for (int i = 0; i < 4; i++) {
            int row = prow + i * 32;
            int grow = bn0 + row;
            bool valid = (grow < 4000);
            const void* src = valid ? (const void*)(Bp + (size_t)grow * LDB + kt * 64 + pk8 * 8)
                                    : (const void*)Bp;
            uint32_t dst = Bb + row * 128 + psw;
            int sz = valid ? 16 : 0;
            asm volatile("cp.async.cg.shared.global [%0], [%1], 16, %2;"
                         :: "r"(dst), "l"(src), "r"(sz));
        }
    };

    const uint32_t xr  = lane & 7;
    const uint32_t hiA = lane >> 4;
    const uint32_t hiB = (lane >> 3) & 1;
    const uint32_t aro = (wm * 32 + (lane & 15)) * 128;
    const uint32_t bro = (wn * 64 + (lane & 7) + ((lane >> 4) << 3)) * 128;

    float c[2][8][4];
#pragma unroll
    for (int mi = 0; mi < 2; mi++)
#pragma unroll
        for (int ni = 0; ni < 8; ni++)
#pragma unroll
            for (int q = 0; q < 4; q++) c[mi][ni][q] = 0.f;

#pragma unroll
    for (int s = 0; s < STAGES - 1; s++) {
        issue(s, s);
        asm volatile("cp.async.commit_group;" ::: "memory");
    }

    for (int kt = 0; kt < NK; ++kt) {
        asm volatile("cp.async.wait_group %0;" :: "n"(STAGES - 2) : "memory");
        __syncthreads();
        if (kt + STAGES - 1 < NK) issue(kt + STAGES - 1, (kt + STAGES - 1) % STAGES);
        asm volatile("cp.async.commit_group;" ::: "memory");

        uint32_t Ab = tbase + (kt % STAGES) * STAGEB;
        uint32_t abase = Ab + aro;
        uint32_t bbase = Ab + ABYTES + bro;
#pragma unroll
        for (int kk = 0; kk < 4; kk++) {
            uint32_t ca = (((uint32_t)(kk * 2) + hiA) ^ xr) << 4;
            uint32_t cb = (((uint32_t)(kk * 2) + hiB) ^ xr) << 4;
            uint32_t a[2][4];
            ldm_x4(a[0], abase + ca);
            ldm_x4(a[1], abase + 2048 + ca);
            uint32_t b[4][4];
#pragma unroll
            for (int p = 0; p < 4; p++) ldm_x4(b[p], bbase + p * 2048 + cb);
#pragma unroll
            for (int mi = 0; mi < 2; mi++)
#pragma unroll
                for (int p = 0; p < 4; p++) {
                    mma16816(c[mi][2 * p],     a[mi], b[p][0], b[p][1]);
                    mma16816(c[mi][2 * p + 1], a[mi], b[p][2], b[p][3]);
                }
        }
        __syncthreads();
    }

    // --------------------------- staged epilogue ---------------------------
    // sigmoid -> half2 -> smem (68-word padded rows, conflict-free) ->
    // coalesced STG.128: 2 rows per instruction, 4 cache lines per instr.
    uint32_t* sst = (uint32_t*)(dsm + (tbase - smem_u32(dsm)));
    const int rowb = wm * 32 + (lane >> 2);
    const int colw = wn * 32 + (lane & 3);
    const __half2 half05 = __float2half2_rn(0.5f);
#pragma unroll
    for (int mi = 0; mi < 2; mi++) {
#pragma unroll
        for (int ni = 0; ni < 8; ni++) {
#pragma unroll
            for (int h = 0; h < 2; h++) {
                float v0 = c[mi][ni][2 * h], v1 = c[mi][ni][2 * h + 1];
                __half2 hv = __floats2half2_rn(0.5f * v0, 0.5f * v1);
                uint32_t u = *(uint32_t*)&hv;
                asm("tanh.approx.f16x2 %0, %0;" : "+r"(u));
                __half2 th = *(__half2*)&u;
                __half2 r = __hfma2(th, half05, half05);
                int rr = rowb + mi * 16 + h * 8;
                int cw = colw + ni * 4;
                sst[rr * 68 + cw] = *(uint32_t*)&r;
            }
        }
    }
    __syncthreads();
    {
        size_t mbase = (size_t)bz * 4000 * 4000;
        const int l16 = lane & 15;
        const int gcol = bn0 + l16 * 8;
        bool cok = (gcol < 4000);
#pragma unroll
        for (int i = 0; i < 8; i++) {
            int row = warp * 16 + i * 2 + (lane >> 4);
            int grow = bm0 + row;
            if (cok && grow < 4000) {
                int4 v = *(int4*)&sst[row * 68 + l16 * 4];
                *(int4*)(g_mask + mbase + (size_t)grow * 4000 + gcol) = v;
            }
        }
    }
}

// =========================================================================
// GEMM2: sa = mask @ V  [fp32 out]  M=4000 N=512 K=4000  (f32 acc, R8-proven)
// =========================================================================
__global__ __launch_bounds__(256, 2) void gemm2_hmma()
{
    constexpr int NK  = 63;      // ceil(4000/64)
    constexpr int LDA = 4000, LDB = 4000;
    constexpr int NMAX = 512;

    extern __shared__ __align__(16) char dsm[];
    uint32_t tbase = (smem_u32(dsm) + 1023u) & ~1023u;

    const int tid  = threadIdx.x;
    const int lane = tid & 31;
    const int warp = tid >> 5;
    const int wm = warp >> 1;
    const int wn = warp & 1;

    const int bz  = blockIdx.z;
    const int bm0 = blockIdx.y * 128;
    const int bn0 = blockIdx.x * 128;
    const __half* A  = g_mask + (size_t)bz * 4000 * 4000;
    const __half* Bp = g_vT   + (size_t)bz * 512 * 4000;

    const int prow = tid >> 3;
    const int pk8  = tid & 7;
    const int psw  = (pk8 ^ (prow & 7)) << 4;

    auto issue = [&](int kt, int s) {
        uint32_t Ab = tbase + s * STAGEB;
        uint32_t Bb = Ab + ABYTES;
        bool kv = (kt * 64 + pk8 * 8) < 4000;
#pragma unroll
        for (int i = 0; i < 4; i++) {
            int row = prow + i * 32;
            int grow = bm0 + row;
            bool valid = kv && (grow < 4000);
            const void* src = valid ? (const void*)(A + (size_t)grow * LDA + kt * 64 + pk8 * 8)
                                    : (const void*)A;
            uint32_t dst = Ab + row * 128 + psw;
            int sz = valid ? 16 : 0;
            asm volatile("cp.async.cg.shared.global [%0], [%1], 16, %2;"
                         :: "r"(dst), "l"(src), "r"(sz));
        }
#pragma unroll
        for (int i = 0; i < 4; i++) {
            int row = prow + i * 32;
            int grow = bn0 + row;
            bool valid = kv && (grow < NMAX);
            const void* src = valid ? (const void*)(Bp + (size_t)grow * LDB + kt * 64 + pk8 * 8)
                                    : (const void*)Bp;
            uint32_t dst = Bb + row * 128 + psw;
            int sz = valid ? 16 : 0;
            asm volatile("cp.async.cg.shared.global [%0], [%1], 16, %2;"
                         :: "r"(dst), "l"(src), "r"(sz));
        }
    };

    const uint32_t xr  = lane & 7;
    const uint32_t hiA = lane >> 4;
    const uint32_t hiB = (lane >> 3) & 1;
    const uint32_t aro = (wm * 32 + (lane & 15)) * 128;
    const uint32_t bro = (wn * 64 + (lane & 7) + ((lane >> 4) << 3)) * 128;

    float c[2][8][4];
#pragma unroll
    for (int mi = 0; mi < 2; mi++)
#pragma unroll
        for (int ni = 0; ni < 8; ni++)
#pragma unroll
            for (int q = 0; q < 4; q++) c[mi][ni][q] = 0.f;

#pragma unroll
    for (int s = 0; s < STAGES - 1; s++) {
        issue(s, s);
        asm volatile("cp.async.commit_group;" ::: "memory");
    }

    for (int kt = 0; kt < NK; ++kt) {
        asm volatile("cp.async.wait_group %0;" :: "n"(STAGES - 2) : "memory");
        __syncthreads();
        if (kt + STAGES - 1 < NK) issue(kt + STAGES - 1, (kt + STAGES - 1) % STAGES);
        asm volatile("cp.async.commit_group;" ::: "memory");

        uint32_t Ab = tbase + (kt % STAGES) * STAGEB;
        uint32_t abase = Ab + aro;
        uint32_t bbase = Ab + ABYTES + bro;
#pragma unroll
        for (int kk = 0; kk < 4; kk++) {
            uint32_t ca = (((uint32_t)(kk * 2) + hiA) ^ xr) << 4;
            uint32_t cb = (((uint32_t)(kk * 2) + hiB) ^ xr) << 4;
            uint32_t a[2][4];
            ldm_x4(a[0], abase + ca);
            ldm_x4(a[1], abase + 2048 + ca);
            uint32_t b[4][4];
#pragma unroll
            for (int p = 0; p < 4; p++) ldm_x4(b[p], bbase + p * 2048 + cb);
#pragma unroll
            for (int mi = 0; mi < 2; mi++)
#pragma unroll
                for (int p = 0; p < 4; p++) {
                    mma16816(c[mi][2 * p],     a[mi], b[p][0], b[p][1]);
                    mma16816(c[mi][2 * p + 1], a[mi], b[p][2], b[p][3]);
                }
        }
        __syncthreads();
    }

    const int rbase = bm0 + wm * 32 + (lane >> 2);
    const int cbase = bn0 + wn * 64 + (lane & 3) * 2;
#pragma unroll
    for (int mi = 0; mi < 2; mi++) {
#pragma unroll
        for (int ni = 0; ni < 8; ni++) {
            int col = cbase + ni * 8;
            size_t cb2 = (size_t)bz * 4000 * 512 + col;
#pragma unroll
            for (int h = 0; h < 2; h++) {
                int row = rbase + mi * 16 + h * 8;
                if (row >= 4000) continue;
                float2 v = make_float2(c[mi][ni][2 * h], c[mi][ni][2 * h + 1]);
                *(float2*)(g_sa + cb2 + (size_t)row * 512) = v;
            }
        }
    }
}

// =========================================================================
// Kernel D: enc 1x1-conv + BN + PReLU + residual.
// smem [d][t] layout (pad 33) -> conflict-free reads (R9-verified, 94us).
// =========================================================================
#define ENC_SMEM (512 * 33 * 4)
__global__ __launch_bounds__(1024) void enc_kernel(
    const float* __restrict__ x,
    const float* __restrict__ W, const float* __restrict__ bias,
    const float* __restrict__ gamma, const float* __restrict__ beta,
    const float* __restrict__ mean,  const float* __restrict__ var,
    const float* __restrict__ alpha,
    float* __restrict__ out)
{
    extern __shared__ float sSa[];            // [512][33] d-major
    __shared__ float sW[512];
    __shared__ float sB[32];
    __shared__ float sAl;

    const int tid = threadIdx.x;
    const int b = blockIdx.y;
    const int t0 = blockIdx.x * 32;

    if (tid < 512) {
        int c = tid >> 4, ch = tid & 15;
        float s = gamma[c] * rsqrtf(var[c] + EPS_);
        sW[tid] = W[c * 16 + ch] * s;
    }
    if (tid < 32) {
        float s = gamma[tid] * rsqrtf(var[tid] + EPS_);
        sB[tid] = bias[tid] * s + beta[tid] - mean[tid] * s;
    }
    if (tid == 0) sAl = alpha[0];

#pragma unroll
    for (int i = 0; i < 4; i++) {
        int v  = tid + i * 1024;
        int tr = v >> 7;
        int d4 = (v & 127) * 4;
        float4 q = *(const float4*)(g_sa + ((size_t)(b * 4000 + t0 + tr)) * 512 + d4);
        sSa[(d4 + 0) * 33 + tr] = q.x;
        sSa[(d4 + 1) * 33 + tr] = q.y;
        sSa[(d4 + 2) * 33 + tr] = q.z;
        sSa[(d4 + 3) * 33 + tr] = q.w;
    }
    __syncthreads();

    const int tl = tid & 31;
    const int f  = tid >> 5;
    const int t  = t0 + tl;

    float sv[16];
#pragma unroll
    for (int ch = 0; ch < 16; ch++) sv[ch] = sSa[(ch * 32 + f) * 33 + tl];

#pragma unroll
    for (int c = 0; c < 32; c++) {
        float acc = sB[c];
#pragma unroll
        for (int ch = 0; ch < 16; ch++) acc += sW[c * 16 + ch] * sv[ch];
        acc = acc > 0.f ? acc : sAl * acc;
        size_t o = ((size_t)((b * 32 + c) * 32 + f)) * 4000 + t;
        out[o] = acc + x[o];
    }
}

// =========================================================================
extern "C" void kernel_launch(void* const* d_in, const int* in_sizes, int n_in,
                              void* d_out, int out_size)
{
    const float* x          = (const float*)d_in[0];
    const float* qkv_W      = (const float*)d_in[1];
    const float* qkv_b      = (const float*)d_in[2];
    const float* qkv_gamma  = (const float*)d_in[3];
    const float* qkv_beta   = (const float*)d_in[4];
    const float* qkv_mean   = (const float*)d_in[5];
    const float* qkv_var    = (const float*)d_in[6];
    const float* qkv_alpha  = (const float*)d_in[7];
    const float* enc_W      = (const float*)d_in[8];
    const float* enc_b      = (const float*)d_in[9];
    const float* enc_gamma  = (const float*)d_in[10];
    const float* enc_beta   = (const float*)d_in[11];
    const float* enc_mean   = (const float*)d_in[12];
    const float* enc_var    = (const float*)d_in[13];
    const float* enc_alpha  = (const float*)d_in[14];
    float* out = (float*)d_out;

    cudaFuncSetAttribute(gemm1_hmma, cudaFuncAttributeMaxDynamicSharedMemorySize, SMEM_GEMM);
    cudaFuncSetAttribute(gemm2_hmma, cudaFuncAttributeMaxDynamicSharedMemorySize, SMEM_GEMM);
    cudaFuncSetAttribute(enc_kernel, cudaFuncAttributeMaxDynamicSharedMemorySize, ENC_SMEM);

    // 0) capture-slot shims (no-ops): put gemm1 on the ncu-captured launch
    noop_kernel<<<1, 32>>>();
    noop_kernel<<<1, 32>>>();
    // 1) q/k/v conv blocks -> token-layout fp16
    qkv_kernel<<<dim3(125, 8), 1024>>>(x, qkv_W, qkv_b, qkv_gamma, qkv_beta,
                                       qkv_mean, qkv_var, qkv_alpha);
    // 2) mask = sigmoid(Q K^T)   [B,4000,4000] fp16
    gemm1_hmma<<<dim3(32, 32, 8), 256, SMEM_GEMM>>>();
    // 3) sa = mask @ V           [B,4000,512] fp32
    gemm2_hmma<<<dim3(4, 32, 8), 256, SMEM_GEMM>>>();
    // 4) enc conv block + residual
    enc_kernel<<<dim3(125, 8), 1024, ENC_SMEM>>>(x, enc_W, enc_b, enc_gamma, enc_beta,
                                                 enc_mean, enc_var, enc_alpha, out);
}

// round 16
// speedup vs baseline: 1.0369x; 1.0231x over previous
#include <cuda_runtime.h>
#include <cuda_fp16.h>
#include <cstdint>
#include <cstddef>

// Problem constants
#define B_   8
#define C_   32
#define F_   32
#define T_   4000
#define CH_  16
#define D_   512
#define KSCALE 0.04419417382415922f   // 1/sqrt(512)
#define EPS_ 1e-5f

// ---------------- device scratch (static, no allocation) ----------------
__device__ __half g_q   [(size_t)B_ * T_ * D_];      // [b][t][d]
__device__ __half g_k   [(size_t)B_ * T_ * D_];      // [b][t][d] (pre-scaled)
__device__ __half g_vT  [(size_t)B_ * D_ * T_];      // [b][d][t]
__device__ __half g_mask[(size_t)B_ * T_ * T_];      // [b][t][s]
__device__ float  g_sa  [(size_t)B_ * T_ * D_];      // [b][t][d]

__device__ __forceinline__ uint32_t smem_u32(const void* p) {
    uint32_t a;
    asm("{ .reg .u64 t; cvta.to.shared.u64 t, %1; cvt.u32.u64 %0, t; }"
        : "=r"(a) : "l"(p));
    return a;
}

// ---- no-op kernel: keeps the ncu capture slot (4th launch) on gemm2 ----
__global__ void noop_kernel() {}

// =========================================================================
// Kernel A: fused q/k/v 1x1-conv + BN + PReLU, output in token layout.
// =========================================================================
__global__ __launch_bounds__(1024) void qkv_kernel(
    const float* __restrict__ x,
    const float* __restrict__ W, const float* __restrict__ bias,
    const float* __restrict__ gamma, const float* __restrict__ beta,
    const float* __restrict__ mean,  const float* __restrict__ var,
    const float* __restrict__ alpha)
{
    __shared__ float sW[3 * 16 * 32];
    __shared__ float sB[3 * 16];
    __shared__ float sAl[3];
    __shared__ __align__(16) __half stage[32 * 520];

    const int tid = threadIdx.x;
    const int b = blockIdx.y;
    const int t0 = blockIdx.x * 32;

    for (int idx = tid; idx < 3 * 16 * 32; idx += 1024) {
        int nc = idx >> 5;
        float s = gamma[nc] * rsqrtf(var[nc] + EPS_);
        sW[idx] = W[idx] * s;
    }
    if (tid < 48) {
        float s = gamma[tid] * rsqrtf(var[tid] + EPS_);
        sB[tid] = bias[tid] * s + beta[tid] - mean[tid] * s;
    }
    if (tid < 3) sAl[tid] = alpha[tid];
    __syncthreads();

    const int tl = tid & 31;
    const int f  = tid >> 5;
    const int t  = t0 + tl;

    float xv[32];
#pragma unroll
    for (int i = 0; i < 32; i++)
        xv[i] = x[((size_t)(b * 32 + i) * 32 + f) * 4000 + t];

    for (int n = 0; n < 2; n++) {
#pragma unroll
        for (int ch = 0; ch < 16; ch++) {
            float acc = sB[n * 16 + ch];
#pragma unroll
            for (int i = 0; i < 32; i++) acc += sW[(n * 16 + ch) * 32 + i] * xv[i];
            acc = acc > 0.f ? acc : sAl[n] * acc;
            if (n == 1) acc *= KSCALE;
            stage[tl * 520 + ch * 32 + f] = __float2half(acc);
        }
        __syncthreads();
        {
            __half* dst = (n == 0) ? g_q : g_k;
            const int w = tid >> 5;
            const int l = tid & 31;
            const __half* src = stage + w * 520 + l * 16;
            __half* dptr = dst + ((size_t)(b * 4000 + t0 + w) * 512) + l * 16;
            int4 v0 = *(const int4*)(src);
            int4 v1 = *(const int4*)(src + 8);
            *(int4*)(dptr) = v0;
            *(int4*)(dptr + 8) = v1;
        }
        __syncthreads();
    }
#pragma unroll
    for (int ch = 0; ch < 16; ch++) {
        float acc = sB[2 * 16 + ch];
#pragma unroll
        for (int i = 0; i < 32; i++) acc += sW[(2 * 16 + ch) * 32 + i] * xv[i];
        acc = acc > 0.f ? acc : sAl[2] * acc;
        int d = ch * 32 + f;
        g_vT[((size_t)b * 512 + d) * 4000 + t] = __float2half(acc);
    }
}

// ======================= shared mma helpers =======================
__device__ __forceinline__ void ldm_x4(uint32_t* r, uint32_t addr) {
    asm volatile("ldmatrix.sync.aligned.m8n8.x4.shared.b16 {%0,%1,%2,%3}, [%4];"
                 : "=r"(r[0]), "=r"(r[1]), "=r"(r[2]), "=r"(r[3]) : "r"(addr));
}
__device__ __forceinline__ void mma16816(float* c, const uint32_t* a,
                                         uint32_t b0, uint32_t b1) {
    asm volatile(
        "mma.sync.aligned.m16n8k16.row.col.f32.f16.f16.f32 "
        "{%0,%1,%2,%3}, {%4,%5,%6,%7}, {%8,%9}, {%0,%1,%2,%3};"
        : "+f"(c[0]), "+f"(c[1]), "+f"(c[2]), "+f"(c[3])
        : "r"(a[0]), "r"(a[1]), "r"(a[2]), "r"(a[3]), "r"(b0), "r"(b1));
}
__device__ __forceinline__ void mma16816_h(uint32_t* c, const uint32_t* a,
                                           uint32_t b0, uint32_t b1) {
    asm volatile(
        "mma.sync.aligned.m16n8k16.row.col.f16.f16.f16.f16 "
        "{%0,%1}, {%2,%3,%4,%5}, {%6,%7}, {%0,%1};"
        : "+r"(c[0]), "+r"(c[1])
        : "r"(a[0]), "r"(a[1]), "r"(a[2]), "r"(a[3]), "r"(b0), "r"(b1));
}

#define ABYTES 16384              // 128 rows x 128B (64 halves)
#define STAGEB (2 * ABYTES)       // A + B

// =========================================================================
// GEMM1: mask = sigmoid(Q K^T)  [fp16 out]  M=4000 N=4000 K=512
// 128x128 tile, BK=64, 2-stage cp.async, 256 thr, fp16 acc, 3 CTAs/SM.
// Epilogue: smem-staged, coalesced 2-rows-per-instr STG.128.
// =========================================================================
#define STAGES1 2
#define SMEM_G1 (1024 + STAGES1 * STAGEB)     // 66560 B -> 3 CTAs/SM

__global__ __launch_bounds__(256, 3) void gemm1_hmma()
{
    constexpr int NK  = 8;       // K=512 / 64
    constexpr int LDA = 512, LDB = 512;

    extern __shared__ __align__(16) char dsm[];
    uint32_t tbase = (smem_u32(dsm) + 1023u) & ~1023u;

    const int tid  = threadIdx.x;
    const int lane = tid & 31;
    const int warp = tid >> 5;
    const int wm = warp >> 1;
    const int wn = warp & 1;

    const int bz  = blockIdx.z;
    const int bm0 = blockIdx.y * 128;
    const int bn0 = blockIdx.x * 128;
    const __half* A  = g_q + (size_t)bz * 4000 * 512;
    const __half* Bp = g_k + (size_t)bz * 4000 * 512;

    const int prow = tid >> 3;
    const int pk8  = tid & 7;
    const int psw  = (pk8 ^ (prow & 7)) << 4;

    auto issue = [&](int kt, int s) {
        uint32_t Ab = tbase + s * STAGEB;
        uint32_t Bb = Ab + ABYTES;
#pragma unroll
        for (int i = 0; i < 4; i++) {
            int row = prow + i * 32;
            int grow = bm0 + row;
            bool valid = (grow < 4000);
            const void* src = valid ? (const void*)(A + (size_t)grow * LDA + kt * 64 + pk8 * 8)
                                    : (const void*)A;
            uint32_t dst = Ab + row * 128 + psw;
            int sz = valid ? 16 : 0;
            asm volatile("cp.async.cg.shared.global [%0], [%1], 16, %2;"
                         :: "r"(dst), "l"(src), "r"(sz));
        }
#pragma unroll
        for (int i = 0; i < 4; i++) {
            int row = prow + i * 32;
            int grow = bn0 + row;
            bool valid = (grow < 4000);
            const void* src = valid ? (const void*)(Bp + (size_t)grow * LDB + kt * 64 + pk8 * 8)
                                    : (const void*)Bp;
            uint32_t dst = Bb + row * 128 + psw;
            int sz = valid ? 16 : 0;
            asm volatile("cp.async.cg.shared.global [%0], [%1], 16, %2;"
                         :: "r"(dst), "l"(src), "r"(sz));
        }
    };

    const uint32_t xr  = lane & 7;
    const uint32_t hiA = lane >> 4;
    const uint32_t hiB = (lane >> 3) & 1;
    const uint32_t aro = (wm * 32 + (lane & 15)) * 128;
    const uint32_t bro = (wn * 64 + (lane & 7) + ((lane >> 4) << 3)) * 128;

    uint32_t c[2][8][2];                       // fp16x2 accumulators
#pragma unroll
    for (int mi = 0; mi < 2; mi++)
#pragma unroll
        for (int ni = 0; ni < 8; ni++)
#pragma unroll
            for (int q = 0; q < 2; q++) c[mi][ni][q] = 0u;

    issue(0, 0);
    asm volatile("cp.async.commit_group;" ::: "memory");

    for (int kt = 0; kt < NK; ++kt) {
        asm volatile("cp.async.wait_group 0;" ::: "memory");
        __syncthreads();
        if (kt + 1 < NK) issue(kt + 1, (kt + 1) % STAGES1);
        asm volatile("cp.async.commit_group;" ::: "memory");

        uint32_t Ab = tbase + (kt % STAGES1) * STAGEB;
        uint32_t abase = Ab + aro;
        uint32_t bbase = Ab + ABYTES + bro;
#pragma unroll
        for (int kk = 0; kk < 4; kk++) {
            uint32_t ca = (((uint32_t)(kk * 2) + hiA) ^ xr) << 4;
            uint32_t cb = (((uint32_t)(kk * 2) + hiB) ^ xr) << 4;
            uint32_t a[2][4];
            ldm_x4(a[0], abase + ca);
            ldm_x4(a[1], abase + 2048 + ca);
            uint32_t b[4][4];
#pragma unroll
            for (int p = 0; p < 4; p++) ldm_x4(b[p], bbase + p * 2048 + cb);
#pragma unroll
            for (int mi = 0; mi < 2; mi++)
#pragma unroll
                for (int p = 0; p < 4; p++) {
                    mma16816_h(c[mi][2 * p],     a[mi], b[p][0], b[p][1]);
                    mma16816_h(c[mi][2 * p + 1], a[mi], b[p][2], b[p][3]);
                }
        }
        __syncthreads();
    }

    // staged epilogue: sigmoid in half2 -> smem (68-word rows) -> STG.128
    uint32_t* sst = (uint32_t*)(dsm + (tbase - smem_u32(dsm)));
    const int rowb = wm * 32 + (lane >> 2);
    const int colw = wn * 32 + (lane & 3);
    const __half2 half05 = __float2half2_rn(0.5f);
#pragma unroll
    for (int mi = 0; mi < 2; mi++) {
#pragma unroll
        for (int ni = 0; ni < 8; ni++) {
#pragma unroll
            for (int h = 0; h < 2; h++) {
                uint32_t u = c[mi][ni][h];
                __half2 hv = __hmul2(*(__half2*)&u, half05);
                uint32_t u2 = *(uint32_t*)&hv;
                asm("tanh.approx.f16x2 %0, %0;" : "+r"(u2));
                __half2 th = *(__half2*)&u2;
                __half2 r = __hfma2(th, half05, half05);
                int rr = rowb + mi * 16 + h * 8;
                int cw = colw + ni * 4;
                sst[rr * 68 + cw] = *(uint32_t*)&r;
            }
        }
    }
    __syncthreads();
    {
        size_t mbase = (size_t)bz * 4000 * 4000;
        const int l16 = lane & 15;
        const int gcol = bn0 + l16 * 8;
        bool cok = (gcol < 4000);
#pragma unroll
        for (int i = 0; i < 8; i++) {
            int row = warp * 16 + i * 2 + (lane >> 4);
            int grow = bm0 + row;
            if (cok && grow < 4000) {
                int4 v = *(int4*)&sst[row * 68 + l16 * 4];
                *(int4*)(g_mask + mbase + (size_t)grow * 4000 + gcol) = v;
            }
        }
    }
}

// =========================================================================
// GEMM2: sa = mask @ V  [fp32 out]  M=4000 N=512 K=4000  (f32 acc, R8-proven)
// =========================================================================
#define STAGES2 3
#define SMEM_G2 (1024 + STAGES2 * STAGEB)

__global__ __launch_bounds__(256, 2) void gemm2_hmma()
{
    constexpr int NK  = 63;      // ceil(4000/64)
    constexpr int LDA = 4000, LDB = 4000;
    constexpr int NMAX = 512;

    extern __shared__ __align__(16) char dsm[];
    uint32_t tbase = (smem_u32(dsm) + 1023u) & ~1023u;

    const int tid  = threadIdx.x;
    const int lane = tid & 31;
    const int warp = tid >> 5;
    const int wm = warp >> 1;
    const int wn = warp & 1;

    const int bz  = blockIdx.z;
    const int bm0 = blockIdx.y * 128;
    const int bn0 = blockIdx.x * 128;
    const __half* A  = g_mask + (size_t)bz * 4000 * 4000;
    const __half* Bp = g_vT   + (size_t)bz * 512 * 4000;

    const int prow = tid >> 3;
    const int pk8  = tid & 7;
    const int psw  = (pk8 ^ (prow & 7)) << 4;

    auto issue = [&](int kt, int s) {
        uint32_t Ab = tbase + s * STAGEB;
        uint32_t Bb = Ab + ABYTES;
        bool kv = (kt * 64 + pk8 * 8) < 4000;
#pragma unroll
        for (int i = 0; i < 4; i++) {
            int row = prow + i * 32;
            int grow = bm0 + row;
            bool valid = kv && (grow < 4000);
            const void* src = valid ? (const void*)(A + (size_t)grow * LDA + kt * 64 + pk8 * 8)
                                    : (const void*)A;
            uint32_t dst = Ab + row * 128 + psw;
            int sz = valid ? 16 : 0;
            asm volatile("cp.async.cg.shared.global [%0], [%1], 16, %2;"
                         :: "r"(dst), "l"(src), "r"(sz));
        }
#pragma unroll
        for (int i = 0; i < 4; i++) {
            int row = prow + i * 32;
            int grow = bn0 + row;
            bool valid = kv && (grow < NMAX);
            const void* src = valid ? (const void*)(Bp + (size_t)grow * LDB + kt * 64 + pk8 * 8)
                                    : (const void*)Bp;
            uint32_t dst = Bb + row * 128 + psw;
            int sz = valid ? 16 : 0;
            asm volatile("cp.async.cg.shared.global [%0], [%1], 16, %2;"
                         :: "r"(dst), "l"(src), "r"(sz));
        }
    };

    const uint32_t xr  = lane & 7;
    const uint32_t hiA = lane >> 4;
    const uint32_t hiB = (lane >> 3) & 1;
    const uint32_t aro = (wm * 32 + (lane & 15)) * 128;
    const uint32_t bro = (wn * 64 + (lane & 7) + ((lane >> 4) << 3)) * 128;

    float c[2][8][4];
#pragma unroll
    for (int mi = 0; mi < 2; mi++)
#pragma unroll
        for (int ni = 0; ni < 8; ni++)
#pragma unroll
            for (int q = 0; q < 4; q++) c[mi][ni][q] = 0.f;

#pragma unroll
    for (int s = 0; s < STAGES2 - 1; s++) {
        issue(s, s);
        asm volatile("cp.async.commit_group;" ::: "memory");
    }

    for (int kt = 0; kt < NK; ++kt) {
        asm volatile("cp.async.wait_group %0;" :: "n"(STAGES2 - 2) : "memory");
        __syncthreads();
        if (kt + STAGES2 - 1 < NK) issue(kt + STAGES2 - 1, (kt + STAGES2 - 1) % STAGES2);
        asm volatile("cp.async.commit_group;" ::: "memory");

        uint32_t Ab = tbase + (kt % STAGES2) * STAGEB;
        uint32_t abase = Ab + aro;
        uint32_t bbase = Ab + ABYTES + bro;
#pragma unroll
        for (int kk = 0; kk < 4; kk++) {
            uint32_t ca = (((uint32_t)(kk * 2) + hiA) ^ xr) << 4;
            uint32_t cb = (((uint32_t)(kk * 2) + hiB) ^ xr) << 4;
            uint32_t a[2][4];
            ldm_x4(a[0], abase + ca);
            ldm_x4(a[1], abase + 2048 + ca);
            uint32_t b[4][4];
#pragma unroll
            for (int p = 0; p < 4; p++) ldm_x4(b[p], bbase + p * 2048 + cb);
#pragma unroll
            for (int mi = 0; mi < 2; mi++)
#pragma unroll
                for (int p = 0; p < 4; p++) {
                    mma16816(c[mi][2 * p],     a[mi], b[p][0], b[p][1]);
                    mma16816(c[mi][2 * p + 1], a[mi], b[p][2], b[p][3]);
                }
        }
        __syncthreads();
    }

    const int rbase = bm0 + wm * 32 + (lane >> 2);
    const int cbase = bn0 + wn * 64 + (lane & 3) * 2;
#pragma unroll
    for (int mi = 0; mi < 2; mi++) {
#pragma unroll
        for (int ni = 0; ni < 8; ni++) {
            int col = cbase + ni * 8;
            size_t cb2 = (size_t)bz * 4000 * 512 + col;
#pragma unroll
            for (int h = 0; h < 2; h++) {
                int row = rbase + mi * 16 + h * 8;
                if (row >= 4000) continue;
                float2 v = make_float2(c[mi][ni][2 * h], c[mi][ni][2 * h + 1]);
                *(float2*)(g_sa + cb2 + (size_t)row * 512) = v;
            }
        }
    }
}

// =========================================================================
// Kernel D: enc 1x1-conv + BN + PReLU + residual.
// smem [d][t] layout (pad 33) -> conflict-free reads (R9-verified, 94us).
// =========================================================================
#define ENC_SMEM (512 * 33 * 4)
__global__ __launch_bounds__(1024) void enc_kernel(
    const float* __restrict__ x,
    const float* __restrict__ W, const float* __restrict__ bias,
    const float* __restrict__ gamma, const float* __restrict__ beta,
    const float* __restrict__ mean,  const float* __restrict__ var,
    const float* __restrict__ alpha,
    float* __restrict__ out)
{
    extern __shared__ float sSa[];            // [512][33] d-major
    __shared__ float sW[512];
    __shared__ float sB[32];
    __shared__ float sAl;

    const int tid = threadIdx.x;
    const int b = blockIdx.y;
    const int t0 = blockIdx.x * 32;

    if (tid < 512) {
        int c = tid >> 4, ch = tid & 15;
        float s = gamma[c] * rsqrtf(var[c] + EPS_);
        sW[tid] = W[c * 16 + ch] * s;
    }
    if (tid < 32) {
        float s = gamma[tid] * rsqrtf(var[tid] + EPS_);
        sB[tid] = bias[tid] * s + beta[tid] - mean[tid] * s;
    }
    if (tid == 0) sAl = alpha[0];

#pragma unroll
    for (int i = 0; i < 4; i++) {
        int v  = tid + i * 1024;
        int tr = v >> 7;
        int d4 = (v & 127) * 4;
        float4 q = *(const float4*)(g_sa + ((size_t)(b * 4000 + t0 + tr)) * 512 + d4);
        sSa[(d4 + 0) * 33 + tr] = q.x;
        sSa[(d4 + 1) * 33 + tr] = q.y;
        sSa[(d4 + 2) * 33 + tr] = q.z;
        sSa[(d4 + 3) * 33 + tr] = q.w;
    }
    __syncthreads();

    const int tl = tid & 31;
    const int f  = tid >> 5;
    const int t  = t0 + tl;

    float sv[16];
#pragma unroll
    for (int ch = 0; ch < 16; ch++) sv[ch] = sSa[(ch * 32 + f) * 33 + tl];

#pragma unroll
    for (int c = 0; c < 32; c++) {
        float acc = sB[c];
#pragma unroll
        for (int ch = 0; ch < 16; ch++) acc += sW[c * 16 + ch] * sv[ch];
        acc = acc > 0.f ? acc : sAl * acc;
        size_t o = ((size_t)((b * 32 + c) * 32 + f)) * 4000 + t;
        out[o] = acc + x[o];
    }
}

// =========================================================================
extern "C" void kernel_launch(void* const* d_in, const int* in_sizes, int n_in,
                              void* d_out, int out_size)
{
    const float* x          = (const float*)d_in[0];
    const float* qkv_W      = (const float*)d_in[1];
    const float* qkv_b      = (const float*)d_in[2];
    const float* qkv_gamma  = (const float*)d_in[3];
    const float* qkv_beta   = (const float*)d_in[4];
    const float* qkv_mean   = (const float*)d_in[5];
    const float* qkv_var    = (const float*)d_in[6];
    const float* qkv_alpha  = (const float*)d_in[7];
    const float* enc_W      = (const float*)d_in[8];
    const float* enc_b      = (const float*)d_in[9];
    const float* enc_gamma  = (const float*)d_in[10];
    const float* enc_beta   = (const float*)d_in[11];
    const float* enc_mean   = (const float*)d_in[12];
    const float* enc_var    = (const float*)d_in[13];
    const float* enc_alpha  = (const float*)d_in[14];
    float* out = (float*)d_out;

    cudaFuncSetAttribute(gemm1_hmma, cudaFuncAttributeMaxDynamicSharedMemorySize, SMEM_G1);
    cudaFuncSetAttribute(gemm2_hmma, cudaFuncAttributeMaxDynamicSharedMemorySize, SMEM_G2);
    cudaFuncSetAttribute(enc_kernel, cudaFuncAttributeMaxDynamicSharedMemorySize, ENC_SMEM);

    // 1) q/k/v conv blocks -> token-layout fp16
    qkv_kernel<<<dim3(125, 8), 1024>>>(x, qkv_W, qkv_b, qkv_gamma, qkv_beta,
                                       qkv_mean, qkv_var, qkv_alpha);
    // 2) mask = sigmoid(Q K^T)   [B,4000,4000] fp16 — fp16 acc, 3 CTAs/SM
    gemm1_hmma<<<dim3(32, 32, 8), 256, SMEM_G1>>>();
    // capture-slot shim: makes gemm2 the 4th launch (profiled next round)
    noop_kernel<<<1, 32>>>();
    // 3) sa = mask @ V           [B,4000,512] fp32
    gemm2_hmma<<<dim3(4, 32, 8), 256, SMEM_G2>>>();
    // 4) enc conv block + residual
    enc_kernel<<<dim3(125, 8), 1024, ENC_SMEM>>>(x, enc_W, enc_b, enc_gamma, enc_beta,
                                                 enc_mean, enc_var, enc_alpha, out);
}